// round 10
// baseline (speedup 1.0000x reference)
#include <cuda_runtime.h>
#include <cuda_fp16.h>
#include <math.h>
#include <stdint.h>

// Problem dims
#define N_  128
#define M_  2048
#define DX_ 64
#define DY_ 8
#define DU_ 256
#define DZ_ 256

// ---------------- device scratch (static, no allocations) ----------------
__device__ __align__(16) __half g_sp1h[DZ_ * DZ_];  // fp16(softplus(Wz1)) [k][z]
__device__ __align__(16) float g_gy0[N_ * DY_];
__device__ __align__(16) float g_c0 [N_ * DZ_];
__device__ __align__(16) float g_gz1[N_ * DZ_];
__device__ __align__(16) float g_gy1[N_ * DY_];
__device__ __align__(16) float g_c1 [N_ * DZ_];
__device__ __align__(16) float g_gk2[N_ * DZ_];     // gz2 * softplus(Wz2)
__device__ __align__(16) float g_w2d[N_ * DY_];     // gy2 * Wy2
__device__ __align__(16) float g_c2 [N_];
__device__ __align__(16) float g_phiA[N_ * M_];     // partial phi, k 0..127
__device__ __align__(16) float g_phiB[N_ * M_];     // partial phi, k 128..255

__device__ __forceinline__ float softplus_f(float x) {
    return fmaxf(x, 0.f) + log1pf(expf(-fabsf(x)));
}

#define CP_ASYNC16(dst, src) \
    asm volatile("cp.async.cg.shared.global [%0], [%1], 16;" \
        :: "r"((uint32_t)(dst)), "l"(src) : "memory")
#define CP_COMMIT() asm volatile("cp.async.commit_group;" ::: "memory")
#define CP_WAIT0()  asm volatile("cp.async.wait_group 0;" ::: "memory")

__device__ __forceinline__ uint32_t smem_u32(const void* p) {
    uint32_t a;
    asm("{ .reg .u64 t; cvta.to.shared.u64 t, %1; cvt.u32.u64 %0, t; }"
        : "=r"(a) : "l"(p));
    return a;
}

// m16n8k16 fp16 MMA, fp32 accumulate
__device__ __forceinline__ void mma_f16(float* c, const uint32_t* a,
                                        uint32_t b0, uint32_t b1) {
    asm volatile(
        "mma.sync.aligned.m16n8k16.row.col.f32.f16.f16.f32 "
        "{%0,%1,%2,%3}, {%4,%5,%6,%7}, {%8,%9}, {%0,%1,%2,%3};"
        : "+f"(c[0]), "+f"(c[1]), "+f"(c[2]), "+f"(c[3])
        : "r"(a[0]), "r"(a[1]), "r"(a[2]), "r"(a[3]), "r"(b0), "r"(b1));
}

#define LDSM_X4(r0, r1, r2, r3, addr) \
    asm volatile("ldmatrix.sync.aligned.m8n8.x4.shared.b16 {%0,%1,%2,%3}, [%4];" \
        : "=r"(r0), "=r"(r1), "=r"(r2), "=r"(r3) : "r"(addr))

__device__ __forceinline__ uint32_t pack_h2(float lo, float hi) {
    __half2 h = __floats2half2_rn(lo, hi);
    return *(uint32_t*)&h;
}

// ---------------- kernel 0: fp16(softplus(Wz1)) ----------------
__global__ void sp1_kernel(const float* __restrict__ Wz1) {
    int i = blockIdx.x * 256 + threadIdx.x;
    g_sp1h[i] = __float2half_rn(softplus_f(Wz1[i]));
}

// ---------------- kernel 1: per-n setup ----------------
__global__ void setup_kernel(
    const float* __restrict__ X,
    const float* __restrict__ Wt0,  const float* __restrict__ bt0,
    const float* __restrict__ Wt1,  const float* __restrict__ bt1,
    const float* __restrict__ Wyu0, const float* __restrict__ byu0,
    const float* __restrict__ Wu0,  const float* __restrict__ b0,
    const float* __restrict__ Wzu1, const float* __restrict__ bzu1,
    const float* __restrict__ Wyu1, const float* __restrict__ byu1,
    const float* __restrict__ Wu1,  const float* __restrict__ b1,
    const float* __restrict__ Wzu2, const float* __restrict__ bzu2,
    const float* __restrict__ Wz2,
    const float* __restrict__ Wyu2, const float* __restrict__ byu2,
    const float* __restrict__ Wy2,
    const float* __restrict__ Wu2,  const float* __restrict__ b2)
{
    __shared__ float xs[DX_], u1s[DU_], u2s[DU_], red[256];
    const int n = blockIdx.x;
    const int k = threadIdx.x;

    if (k < DX_) xs[k] = X[n * DX_ + k];
    __syncthreads();

    float s = bt0[k];
    #pragma unroll 8
    for (int d = 0; d < DX_; d++) s = fmaf(xs[d], Wt0[k * DX_ + d], s);
    u1s[k] = fmaxf(s, 0.f);
    __syncthreads();

    s = bt1[k];
    #pragma unroll 8
    for (int z = 0; z < DU_; z++) s = fmaf(u1s[z], Wt1[k * DU_ + z], s);
    float u2v = fmaxf(s, 0.f);
    u2s[k] = u2v;

    if (k < DY_) {
        float t = byu0[k];
        #pragma unroll 8
        for (int d = 0; d < DX_; d++) t = fmaf(xs[d], Wyu0[k * DX_ + d], t);
        g_gy0[n * DY_ + k] = t;
        t = byu1[k];
        #pragma unroll 8
        for (int z = 0; z < DU_; z++) t = fmaf(u1s[z], Wyu1[k * DU_ + z], t);
        g_gy1[n * DY_ + k] = t;
    }
    s = b0[k];
    #pragma unroll 8
    for (int d = 0; d < DX_; d++) s = fmaf(xs[d], Wu0[k * DX_ + d], s);
    g_c0[n * DZ_ + k] = s;
    s = bzu1[k];
    #pragma unroll 8
    for (int z = 0; z < DU_; z++) s = fmaf(u1s[z], Wzu1[k * DU_ + z], s);
    g_gz1[n * DZ_ + k] = fmaxf(s, 0.f);
    s = b1[k];
    #pragma unroll 8
    for (int z = 0; z < DU_; z++) s = fmaf(u1s[z], Wu1[k * DU_ + z], s);
    g_c1[n * DZ_ + k] = s;
    __syncthreads();

    s = bzu2[k];
    #pragma unroll 8
    for (int z = 0; z < DU_; z++) s = fmaf(u2s[z], Wzu2[k * DU_ + z], s);
    g_gk2[n * DZ_ + k] = fmaxf(s, 0.f) * softplus_f(Wz2[k]);

    if (k < DY_) {
        float t = byu2[k];
        #pragma unroll 8
        for (int z = 0; z < DU_; z++) t = fmaf(u2s[z], Wyu2[k * DU_ + z], t);
        g_w2d[n * DY_ + k] = t * Wy2[k];
    }

    red[k] = u2v * Wu2[k];
    __syncthreads();
    for (int st = 128; st > 0; st >>= 1) {
        if (k < st) red[k] += red[k + st];
        __syncthreads();
    }
    if (k == 0) g_c2[n] = red[0] + b2[0];
}

// ---------------- kernel 2: fp16 HMMA GEMM + partial phi ----------------
// grid = (32, 2, 128): x -> 64-row m-tile, y -> k-half (128 cols), z -> n.
// CTA: 64m x 128k, 8 warps: wm = wid&1 (32 m rows), wq = wid>>1 (32 k cols).
// K loop: 4 chunks of 64 z + 1 k16 pseudo chunk; double buffered, ldmatrix frags.
// Row stride 144 B -> conflict-free ldmatrix. Occupancy 3.

#define RS    144
#define WROWS 128
#define SM_W     0                  // 2 x 128*144 = 36864
#define SM_A     36864              // 2 x 64*144  = 18432
#define SM_WY0F  55296              // 256 x 12 floats = 12288
#define SM_C0    67584              // 256 floats
#define SM_GZ1   68608              // 256 floats
#define SM_C1    69632              // 128 floats
#define SM_GK2   70144              // 128 floats
#define SM_GY1   70656              // pad 64
#define SM_YW    70720              // pad 64 (unused here)
#define SM_PHI   70784              // 256 floats
#define SMEM_BYTES 71808
#define WBUF  18432                 // 128*144
#define ABUF  9216                  // 64*144

extern __shared__ __align__(16) char smem[];

// fill one 64-z A chunk: thread owns row mrow, z quarter s (16 z)
__device__ __forceinline__ void fill_A64(char* Adst, int z0,
                                         const float* wy0f, const float* c0s,
                                         const float* gz1s, const float* ur,
                                         int mrow, int s)
{
    float o[16];
    #pragma unroll
    for (int jj = 0; jj < 16; ++jj) {
        const int j = (jj + s) & 15;           // bank-rotation schedule
        const int z = z0 + s * 16 + j;
        const float4 w0 = *(const float4*)(wy0f + z * 12);
        const float4 w1 = *(const float4*)(wy0f + z * 12 + 4);
        float v = c0s[z];
        v = fmaf(ur[0], w0.x, v); v = fmaf(ur[1], w0.y, v);
        v = fmaf(ur[2], w0.z, v); v = fmaf(ur[3], w0.w, v);
        v = fmaf(ur[4], w1.x, v); v = fmaf(ur[5], w1.y, v);
        v = fmaf(ur[6], w1.z, v); v = fmaf(ur[7], w1.w, v);
        o[j] = fmaxf(v, 0.f) * gz1s[z];
    }
    uint4 p0, p1;
    p0.x = pack_h2(o[0],  o[1]);  p0.y = pack_h2(o[2],  o[3]);
    p0.z = pack_h2(o[4],  o[5]);  p0.w = pack_h2(o[6],  o[7]);
    p1.x = pack_h2(o[8],  o[9]);  p1.y = pack_h2(o[10], o[11]);
    p1.z = pack_h2(o[12], o[13]); p1.w = pack_h2(o[14], o[15]);
    char* dst = Adst + mrow * RS + s * 32;
    *(uint4*)(dst)      = p0;
    *(uint4*)(dst + 16) = p1;
}

__global__ __launch_bounds__(256, 3) void main_mma_kernel(
    const float* __restrict__ U,
    const float* __restrict__ Wy0,
    const float* __restrict__ Wy1)
{
    const int tid  = threadIdx.x;
    const int lane = tid & 31;
    const int wid  = tid >> 5;
    const int g    = lane >> 2;     // groupID
    const int t4   = lane & 3;      // thread-in-group
    const int wm   = wid & 1;       // warp m-group (32 rows)
    const int wq   = wid >> 1;      // warp k-col group (32 cols)
    const int n    = blockIdx.z;
    const int nh   = blockIdx.y;
    const int m0   = blockIdx.x * 64;
    const int k0   = nh * 128;

    float* wy0f = (float*)(smem + SM_WY0F);
    float* c0s  = (float*)(smem + SM_C0);
    float* gz1s = (float*)(smem + SM_GZ1);
    float* c1s  = (float*)(smem + SM_C1);
    float* gk2s = (float*)(smem + SM_GK2);
    float* gy1s = (float*)(smem + SM_GY1);
    float* phiB = (float*)(smem + SM_PHI);
    const uint32_t sb = smem_u32(smem);

    // A-fill assignment
    const int mrow = tid >> 2;      // 0..63
    const int s    = tid & 3;       // z quarter

    // ldmatrix per-lane base addresses (buf 0)
    const int mi = lane >> 3, r = lane & 7;
    uint32_t a_base[2], b_base[2];
    #pragma unroll
    for (int i = 0; i < 2; ++i)
        a_base[i] = sb + SM_A + (uint32_t)((wm * 32 + i * 16 + (mi & 1) * 8 + r) * RS
                                           + (mi >> 1) * 16);
    #pragma unroll
    for (int jp = 0; jp < 2; ++jp)
        b_base[jp] = sb + SM_W + (uint32_t)((wq * 32 + jp * 16 + (mi >> 1) * 8 + r) * RS
                                            + (mi & 1) * 16);

    // ---- kick off W chunk 0 cp.async (128 rows x 64 z) ----
    {
        const uint32_t Wdst = sb + SM_W;
        #pragma unroll
        for (int it = 0; it < 4; ++it) {
            int idx = it * 256 + tid;
            int q = idx >> 3, seg = idx & 7;
            CP_ASYNC16(Wdst + (uint32_t)(q * RS + seg * 16),
                       &g_sp1h[(k0 + q) * 256 + seg * 8]);
        }
        CP_COMMIT();
    }

    // ---- prologue: per-n consts ----
    c0s[tid]  = g_c0 [n * DZ_ + tid];
    gz1s[tid] = g_gz1[n * DZ_ + tid];
    if (tid < 128) {
        c1s[tid]  = g_c1 [n * DZ_ + k0 + tid];
        gk2s[tid] = g_gk2[n * DZ_ + k0 + tid];
    }
    if (tid < DY_) gy1s[tid] = g_gy1[n * DY_ + tid];
    {   // wy0f[z][d] = Wy0[z][d] * gy0[n][d], stride 12 floats
        const int z = tid;
        float4 wa = *(const float4*)&Wy0[z * 8];
        float4 wb = *(const float4*)&Wy0[z * 8 + 4];
        float4 ga = *(const float4*)&g_gy0[n * DY_];
        float4 gb = *(const float4*)&g_gy0[n * DY_ + 4];
        *(float4*)(wy0f + z * 12)     = make_float4(wa.x*ga.x, wa.y*ga.y, wa.z*ga.z, wa.w*ga.w);
        *(float4*)(wy0f + z * 12 + 4) = make_float4(wb.x*gb.x, wb.y*gb.y, wb.z*gb.z, wb.w*gb.w);
    }
    float ur[8];
    {
        float4 u0 = *(const float4*)&U[(m0 + mrow) * 8];
        float4 u1 = *(const float4*)&U[(m0 + mrow) * 8 + 4];
        ur[0]=u0.x; ur[1]=u0.y; ur[2]=u0.z; ur[3]=u0.w;
        ur[4]=u1.x; ur[5]=u1.y; ur[6]=u1.z; ur[7]=u1.w;
    }
    __syncthreads();

    fill_A64(smem + SM_A, 0, wy0f, c0s, gz1s, ur, mrow, s);
    CP_WAIT0();
    __syncthreads();

    float acc[2][4][4];
    #pragma unroll
    for (int i = 0; i < 2; ++i)
        #pragma unroll
        for (int j = 0; j < 4; ++j)
            #pragma unroll
            for (int q = 0; q < 4; ++q) acc[i][j][q] = 0.f;

    // ---- main loop: 4 real 64-z chunks + 1 pseudo k16 chunk ----
    #pragma unroll
    for (int c = 0; c < 5; ++c) {
        const int buf = c & 1, nb = buf ^ 1;

        if (c < 4) {
            if (c + 1 < 4) {
                const int z0n = (c + 1) * 64;
                const uint32_t Wdst = sb + SM_W + nb * WBUF;
                #pragma unroll
                for (int it = 0; it < 4; ++it) {
                    int idx = it * 256 + tid;
                    int q = idx >> 3, seg = idx & 7;
                    CP_ASYNC16(Wdst + (uint32_t)(q * RS + seg * 16),
                               &g_sp1h[(k0 + q) * 256 + z0n + seg * 8]);
                }
                CP_COMMIT();
                fill_A64(smem + SM_A + nb * ABUF, z0n, wy0f, c0s, gz1s, ur, mrow, s);
            } else {
                // pseudo chunk (k16): A[m][0..7]=U, 8..15=0; W[q][0..7]=Wy1*gy1
                char* Adst = smem + SM_A + nb * ABUF;
                if (s == 0) {
                    uint4 av, zv;
                    av.x = pack_h2(ur[0], ur[1]); av.y = pack_h2(ur[2], ur[3]);
                    av.z = pack_h2(ur[4], ur[5]); av.w = pack_h2(ur[6], ur[7]);
                    zv = make_uint4(0, 0, 0, 0);
                    *(uint4*)(Adst + mrow * RS)      = av;
                    *(uint4*)(Adst + mrow * RS + 16) = zv;
                }
                if (tid < WROWS) {
                    char* Wdst = smem + SM_W + nb * WBUF;
                    const int q = tid;
                    float4 w0 = *(const float4*)&Wy1[(k0 + q) * 8];
                    float4 w1 = *(const float4*)&Wy1[(k0 + q) * 8 + 4];
                    uint4 wv;
                    wv.x = pack_h2(w0.x * gy1s[0], w0.y * gy1s[1]);
                    wv.y = pack_h2(w0.z * gy1s[2], w0.w * gy1s[3]);
                    wv.z = pack_h2(w1.x * gy1s[4], w1.y * gy1s[5]);
                    wv.w = pack_h2(w1.z * gy1s[6], w1.w * gy1s[7]);
                    *(uint4*)(Wdst + q * RS)      = wv;
                    *(uint4*)(Wdst + q * RS + 16) = make_uint4(0, 0, 0, 0);
                }
            }
        }

        // MMA on current buffer
        {
            const uint32_t aoff = buf * ABUF;
            const uint32_t woff = buf * WBUF;
            const int nks = (c == 4) ? 1 : 4;
            #pragma unroll
            for (int ks = 0; ks < 4; ++ks) {
                if (ks >= nks) break;
                const uint32_t kb = ks * 32;
                uint32_t a0[4], a1[4];
                LDSM_X4(a0[0], a0[1], a0[2], a0[3], a_base[0] + aoff + kb);
                LDSM_X4(a1[0], a1[1], a1[2], a1[3], a_base[1] + aoff + kb);
                #pragma unroll
                for (int jp = 0; jp < 2; ++jp) {
                    uint32_t b[4];
                    LDSM_X4(b[0], b[1], b[2], b[3], b_base[jp] + woff + kb);
                    mma_f16(acc[0][jp * 2],     a0, b[0], b[1]);
                    mma_f16(acc[1][jp * 2],     a1, b[0], b[1]);
                    mma_f16(acc[0][jp * 2 + 1], a0, b[2], b[3]);
                    mma_f16(acc[1][jp * 2 + 1], a1, b[2], b[3]);
                }
            }
        }
        if (c < 3) CP_WAIT0();
        __syncthreads();
    }

    // ---- epilogue: partial phi over this CTA's 128 k ----
    float p[4] = {0.f, 0.f, 0.f, 0.f};
    #pragma unroll
    for (int j = 0; j < 4; ++j) {
        const int q = wq * 32 + j * 8 + 2 * t4;
        const float ca = c1s[q],  cb = c1s[q + 1];
        const float ga = gk2s[q], gb = gk2s[q + 1];
        #pragma unroll
        for (int i = 0; i < 2; ++i) {
            p[i*2+0] = fmaf(fmaxf(acc[i][j][0] + ca, 0.f), ga, p[i*2+0]);
            p[i*2+0] = fmaf(fmaxf(acc[i][j][1] + cb, 0.f), gb, p[i*2+0]);
            p[i*2+1] = fmaf(fmaxf(acc[i][j][2] + ca, 0.f), ga, p[i*2+1]);
            p[i*2+1] = fmaf(fmaxf(acc[i][j][3] + cb, 0.f), gb, p[i*2+1]);
        }
    }
    #pragma unroll
    for (int idx = 0; idx < 4; ++idx) {
        float v = p[idx];
        v += __shfl_xor_sync(0xffffffffu, v, 1);
        v += __shfl_xor_sync(0xffffffffu, v, 2);
        if (t4 == 0) {
            const int i = idx >> 1, h = idx & 1;
            phiB[wq * 64 + wm * 32 + i * 16 + h * 8 + g] = v;
        }
    }
    __syncthreads();
    if (tid < 64) {
        float phi = phiB[tid] + phiB[64 + tid] + phiB[128 + tid] + phiB[192 + tid];
        float* dst = nh ? g_phiB : g_phiA;
        dst[n * M_ + m0 + tid] = phi;
    }
}

// ---------------- kernel 3: slack + row-wise stable logsumexp ----------------
__global__ void lse_kernel(const float* __restrict__ U,
                           const float* __restrict__ Y,
                           float* __restrict__ out) {
    __shared__ float yw[8];
    __shared__ float wred[8];
    __shared__ float bmax_s;
    const int n = blockIdx.x, tid = threadIdx.x;
    const int lane = tid & 31, warp = tid >> 5;

    if (tid < 8) yw[tid] = Y[n * DY_ + tid] - g_w2d[n * DY_ + tid];
    __syncthreads();
    const float c2 = g_c2[n];

    float s[8];
    #pragma unroll
    for (int i = 0; i < 8; i++) {
        const int m = i * 256 + tid;
        float4 u0 = *(const float4*)&U[m * 8];
        float4 u1 = *(const float4*)&U[m * 8 + 4];
        float v = -c2 - g_phiA[n * M_ + m] - g_phiB[n * M_ + m];
        v = fmaf(u0.x, yw[0], v); v = fmaf(u0.y, yw[1], v);
        v = fmaf(u0.z, yw[2], v); v = fmaf(u0.w, yw[3], v);
        v = fmaf(u1.x, yw[4], v); v = fmaf(u1.y, yw[5], v);
        v = fmaf(u1.z, yw[6], v); v = fmaf(u1.w, yw[7], v);
        s[i] = v;
    }

    float mx = s[0];
    #pragma unroll
    for (int i = 1; i < 8; i++) mx = fmaxf(mx, s[i]);
    #pragma unroll
    for (int off = 16; off; off >>= 1)
        mx = fmaxf(mx, __shfl_xor_sync(0xffffffffu, mx, off));
    if (lane == 0) wred[warp] = mx;
    __syncthreads();
    if (tid == 0) {
        float m2 = wred[0];
        #pragma unroll
        for (int w = 1; w < 8; w++) m2 = fmaxf(m2, wred[w]);
        bmax_s = m2;
    }
    __syncthreads();
    const float bmax = bmax_s;

    float sum = 0.f;
    #pragma unroll
    for (int i = 0; i < 8; i++) sum += expf((s[i] - bmax) * 100.f);
    #pragma unroll
    for (int off = 16; off; off >>= 1)
        sum += __shfl_xor_sync(0xffffffffu, sum, off);
    __syncthreads();
    if (lane == 0) wred[warp] = sum;
    __syncthreads();
    if (tid == 0) {
        float tot = 0.f;
        #pragma unroll
        for (int w = 0; w < 8; w++) tot += wred[w];
        out[n] = 0.01f * (logf(tot) - logf(2048.0f)) + bmax;
    }
}

// ---------------- launch ----------------
extern "C" void kernel_launch(void* const* d_in, const int* in_sizes, int n_in,
                              void* d_out, int out_size) {
    const float* X    = (const float*)d_in[0];
    const float* U    = (const float*)d_in[1];
    const float* Y    = (const float*)d_in[2];
    const float* Wt0  = (const float*)d_in[3];
    const float* bt0  = (const float*)d_in[4];
    const float* Wt1  = (const float*)d_in[5];
    const float* bt1  = (const float*)d_in[6];
    const float* Wyu0 = (const float*)d_in[7];
    const float* byu0 = (const float*)d_in[8];
    const float* Wy0  = (const float*)d_in[9];
    const float* Wu0  = (const float*)d_in[10];
    const float* b0   = (const float*)d_in[11];
    const float* Wzu1 = (const float*)d_in[12];
    const float* bzu1 = (const float*)d_in[13];
    const float* Wz1  = (const float*)d_in[14];
    const float* Wyu1 = (const float*)d_in[15];
    const float* byu1 = (const float*)d_in[16];
    const float* Wy1  = (const float*)d_in[17];
    const float* Wu1  = (const float*)d_in[18];
    const float* b1   = (const float*)d_in[19];
    const float* Wzu2 = (const float*)d_in[20];
    const float* bzu2 = (const float*)d_in[21];
    const float* Wz2  = (const float*)d_in[22];
    const float* Wyu2 = (const float*)d_in[23];
    const float* byu2 = (const float*)d_in[24];
    const float* Wy2  = (const float*)d_in[25];
    const float* Wu2  = (const float*)d_in[26];
    const float* b2   = (const float*)d_in[27];

    cudaFuncSetAttribute(main_mma_kernel,
                         cudaFuncAttributeMaxDynamicSharedMemorySize, SMEM_BYTES);

    sp1_kernel<<<256, 256>>>(Wz1);
    setup_kernel<<<128, 256>>>(X, Wt0, bt0, Wt1, bt1, Wyu0, byu0, Wu0, b0,
                               Wzu1, bzu1, Wyu1, byu1, Wu1, b1,
                               Wzu2, bzu2, Wz2, Wyu2, byu2, Wy2, Wu2, b2);
    dim3 grid(32, 2, 128);
    main_mma_kernel<<<grid, 256, SMEM_BYTES>>>(U, Wy0, Wy1);
    lse_kernel<<<128, 256>>>(U, Y, (float*)d_out);
}

// round 11
// speedup vs baseline: 1.3080x; 1.3080x over previous
#include <cuda_runtime.h>
#include <cuda_fp16.h>
#include <math.h>
#include <stdint.h>

// Problem dims
#define N_  128
#define M_  2048
#define DX_ 64
#define DY_ 8
#define DU_ 256
#define DZ_ 256

// ---------------- device scratch (static, no allocations) ----------------
__device__ __align__(16) __half g_sp1h[DZ_ * DZ_];  // fp16(softplus(Wz1)) [k][z]
__device__ __align__(16) float g_gy0[N_ * DY_];
__device__ __align__(16) float g_c0 [N_ * DZ_];
__device__ __align__(16) float g_gz1[N_ * DZ_];
__device__ __align__(16) float g_gy1[N_ * DY_];
__device__ __align__(16) float g_c1 [N_ * DZ_];
__device__ __align__(16) float g_gk2[N_ * DZ_];     // gz2 * softplus(Wz2)
__device__ __align__(16) float g_w2d[N_ * DY_];     // gy2 * Wy2
__device__ __align__(16) float g_c2 [N_];
__device__ __align__(16) float g_slack[N_ * M_];

__device__ __forceinline__ float softplus_f(float x) {
    return fmaxf(x, 0.f) + log1pf(expf(-fabsf(x)));
}

#define CP_ASYNC16(dst, src) \
    asm volatile("cp.async.cg.shared.global [%0], [%1], 16;" \
        :: "r"((uint32_t)(dst)), "l"(src) : "memory")
#define CP_COMMIT() asm volatile("cp.async.commit_group;" ::: "memory")
#define CP_WAIT0()  asm volatile("cp.async.wait_group 0;" ::: "memory")

__device__ __forceinline__ uint32_t smem_u32(const void* p) {
    uint32_t a;
    asm("{ .reg .u64 t; cvta.to.shared.u64 t, %1; cvt.u32.u64 %0, t; }"
        : "=r"(a) : "l"(p));
    return a;
}

// m16n8k16 fp16 MMA, fp32 accumulate
__device__ __forceinline__ void mma_f16(float* c, const uint32_t* a,
                                        uint32_t b0, uint32_t b1) {
    asm volatile(
        "mma.sync.aligned.m16n8k16.row.col.f32.f16.f16.f32 "
        "{%0,%1,%2,%3}, {%4,%5,%6,%7}, {%8,%9}, {%0,%1,%2,%3};"
        : "+f"(c[0]), "+f"(c[1]), "+f"(c[2]), "+f"(c[3])
        : "r"(a[0]), "r"(a[1]), "r"(a[2]), "r"(a[3]), "r"(b0), "r"(b1));
}

#define LDSM_X4(r0, r1, r2, r3, addr) \
    asm volatile("ldmatrix.sync.aligned.m8n8.x4.shared.b16 {%0,%1,%2,%3}, [%4];" \
        : "=r"(r0), "=r"(r1), "=r"(r2), "=r"(r3) : "r"(addr))

__device__ __forceinline__ uint32_t pack_h2(float lo, float hi) {
    __half2 h = __floats2half2_rn(lo, hi);
    return *(uint32_t*)&h;
}

// ---------------- kernel 1: per-n setup (+ fp16 softplus(Wz1) fold-in) ----------------
__global__ void setup_kernel(
    const float* __restrict__ X,
    const float* __restrict__ Wt0,  const float* __restrict__ bt0,
    const float* __restrict__ Wt1,  const float* __restrict__ bt1,
    const float* __restrict__ Wyu0, const float* __restrict__ byu0,
    const float* __restrict__ Wu0,  const float* __restrict__ b0,
    const float* __restrict__ Wzu1, const float* __restrict__ bzu1,
    const float* __restrict__ Wyu1, const float* __restrict__ byu1,
    const float* __restrict__ Wu1,  const float* __restrict__ b1,
    const float* __restrict__ Wzu2, const float* __restrict__ bzu2,
    const float* __restrict__ Wz2,
    const float* __restrict__ Wyu2, const float* __restrict__ byu2,
    const float* __restrict__ Wy2,
    const float* __restrict__ Wu2,  const float* __restrict__ b2,
    const float* __restrict__ Wz1)
{
    __shared__ float xs[DX_], u1s[DU_], u2s[DU_], red[256];
    const int n = blockIdx.x;
    const int k = threadIdx.x;

    // folded sp1: 65536 elems / 128 CTAs = 512 per CTA
    {
        int i0 = n * 512 + k;
        g_sp1h[i0]       = __float2half_rn(softplus_f(Wz1[i0]));
        g_sp1h[i0 + 256] = __float2half_rn(softplus_f(Wz1[i0 + 256]));
    }

    if (k < DX_) xs[k] = X[n * DX_ + k];
    __syncthreads();

    float s = bt0[k];
    #pragma unroll 8
    for (int d = 0; d < DX_; d++) s = fmaf(xs[d], Wt0[k * DX_ + d], s);
    u1s[k] = fmaxf(s, 0.f);
    __syncthreads();

    s = bt1[k];
    #pragma unroll 8
    for (int z = 0; z < DU_; z++) s = fmaf(u1s[z], Wt1[k * DU_ + z], s);
    float u2v = fmaxf(s, 0.f);
    u2s[k] = u2v;

    if (k < DY_) {
        float t = byu0[k];
        #pragma unroll 8
        for (int d = 0; d < DX_; d++) t = fmaf(xs[d], Wyu0[k * DX_ + d], t);
        g_gy0[n * DY_ + k] = t;
        t = byu1[k];
        #pragma unroll 8
        for (int z = 0; z < DU_; z++) t = fmaf(u1s[z], Wyu1[k * DU_ + z], t);
        g_gy1[n * DY_ + k] = t;
    }
    s = b0[k];
    #pragma unroll 8
    for (int d = 0; d < DX_; d++) s = fmaf(xs[d], Wu0[k * DX_ + d], s);
    g_c0[n * DZ_ + k] = s;
    s = bzu1[k];
    #pragma unroll 8
    for (int z = 0; z < DU_; z++) s = fmaf(u1s[z], Wzu1[k * DU_ + z], s);
    g_gz1[n * DZ_ + k] = fmaxf(s, 0.f);
    s = b1[k];
    #pragma unroll 8
    for (int z = 0; z < DU_; z++) s = fmaf(u1s[z], Wu1[k * DU_ + z], s);
    g_c1[n * DZ_ + k] = s;
    __syncthreads();

    s = bzu2[k];
    #pragma unroll 8
    for (int z = 0; z < DU_; z++) s = fmaf(u2s[z], Wzu2[k * DU_ + z], s);
    g_gk2[n * DZ_ + k] = fmaxf(s, 0.f) * softplus_f(Wz2[k]);

    if (k < DY_) {
        float t = byu2[k];
        #pragma unroll 8
        for (int z = 0; z < DU_; z++) t = fmaf(u2s[z], Wyu2[k * DU_ + z], t);
        g_w2d[n * DY_ + k] = t * Wy2[k];
    }

    red[k] = u2v * Wu2[k];
    __syncthreads();
    for (int st = 128; st > 0; st >>= 1) {
        if (k < st) red[k] += red[k + st];
        __syncthreads();
    }
    if (k == 0) g_c2[n] = red[0] + b2[0];
}

// ---------------- kernel 2: fp16 HMMA GEMM + full phi + slack ----------------
// grid = (32, 128): x -> 64-row m-tile, y -> n.  CTA: 64m x 256k_out.
// 8 warps: wm = wid&1 (32 m rows), wq = wid>>1 (64 k cols).
// K loop: 4 chunks of 64 z + 1 k16 pseudo chunk; double buffered, ldmatrix frags.
// Row stride 144 B (9 x 16B) -> conflict-free ldmatrix.
// Round order: cp.async issue -> MMA issue -> fill -> wait/barrier.

#define RS    144                   // row stride bytes
#define SM_W     0                  // 2 x 256*144 = 73728
#define SM_A     73728              // 2 x 64*144  = 18432
#define SM_WY0F  92160              // 256 x 12 floats = 12288
#define SM_C0    104448             // 256 floats
#define SM_GZ1   105472
#define SM_C1    106496
#define SM_GK2   107520
#define SM_GY1   108544             // 8 floats (pad 64B)
#define SM_YW    108608
#define SM_PHI   108672             // 256 floats
#define SMEM_BYTES 109696
#define WBUF  36864                 // 256*144
#define ABUF  9216                  // 64*144

extern __shared__ __align__(16) char smem[];

// fill one 64-z A chunk: thread owns row mrow, z quarter s (16 z)
__device__ __forceinline__ void fill_A64(char* Adst, int z0,
                                         const float* wy0f, const float* c0s,
                                         const float* gz1s, const float* ur,
                                         int mrow, int s)
{
    float o[16];
    #pragma unroll
    for (int jj = 0; jj < 16; ++jj) {
        const int j = (jj + s) & 15;           // bank-rotation schedule
        const int z = z0 + s * 16 + j;
        const float4 w0 = *(const float4*)(wy0f + z * 12);
        const float4 w1 = *(const float4*)(wy0f + z * 12 + 4);
        float v = c0s[z];
        v = fmaf(ur[0], w0.x, v); v = fmaf(ur[1], w0.y, v);
        v = fmaf(ur[2], w0.z, v); v = fmaf(ur[3], w0.w, v);
        v = fmaf(ur[4], w1.x, v); v = fmaf(ur[5], w1.y, v);
        v = fmaf(ur[6], w1.z, v); v = fmaf(ur[7], w1.w, v);
        o[j] = fmaxf(v, 0.f) * gz1s[z];
    }
    uint4 p0, p1;
    p0.x = pack_h2(o[0],  o[1]);  p0.y = pack_h2(o[2],  o[3]);
    p0.z = pack_h2(o[4],  o[5]);  p0.w = pack_h2(o[6],  o[7]);
    p1.x = pack_h2(o[8],  o[9]);  p1.y = pack_h2(o[10], o[11]);
    p1.z = pack_h2(o[12], o[13]); p1.w = pack_h2(o[14], o[15]);
    char* dst = Adst + mrow * RS + s * 32;
    *(uint4*)(dst)      = p0;
    *(uint4*)(dst + 16) = p1;
}

__global__ __launch_bounds__(256, 2) void main_mma_kernel(
    const float* __restrict__ U,
    const float* __restrict__ Y,
    const float* __restrict__ Wy0,
    const float* __restrict__ Wy1)
{
    const int tid  = threadIdx.x;
    const int lane = tid & 31;
    const int wid  = tid >> 5;
    const int g    = lane >> 2;     // groupID
    const int t4   = lane & 3;      // thread-in-group
    const int wm   = wid & 1;       // warp m-group (32 rows)
    const int wq   = wid >> 1;      // warp k-col group (64 cols)
    const int n    = blockIdx.y;
    const int m0   = blockIdx.x * 64;

    float* wy0f = (float*)(smem + SM_WY0F);
    float* c0s  = (float*)(smem + SM_C0);
    float* gz1s = (float*)(smem + SM_GZ1);
    float* c1s  = (float*)(smem + SM_C1);
    float* gk2s = (float*)(smem + SM_GK2);
    float* gy1s = (float*)(smem + SM_GY1);
    float* yws  = (float*)(smem + SM_YW);
    float* phiB = (float*)(smem + SM_PHI);
    const uint32_t sb = smem_u32(smem);

    // A-fill assignment
    const int mrow = tid >> 2;      // 0..63
    const int s    = tid & 3;       // z quarter

    // ldmatrix per-lane base addresses (buf 0)
    const int mi = lane >> 3, r = lane & 7;
    uint32_t a_base[2], b_base[4];
    #pragma unroll
    for (int i = 0; i < 2; ++i)
        a_base[i] = sb + SM_A + (uint32_t)((wm * 32 + i * 16 + (mi & 1) * 8 + r) * RS
                                           + (mi >> 1) * 16);
    #pragma unroll
    for (int jp = 0; jp < 4; ++jp)
        b_base[jp] = sb + SM_W + (uint32_t)((wq * 64 + jp * 16 + (mi >> 1) * 8 + r) * RS
                                            + (mi & 1) * 16);

    // ---- kick off W chunk 0 cp.async ----
    {
        const uint32_t Wdst = sb + SM_W;
        #pragma unroll
        for (int it = 0; it < 8; ++it) {
            int idx = it * 256 + tid;
            int q = idx >> 3, seg = idx & 7;
            CP_ASYNC16(Wdst + (uint32_t)(q * RS + seg * 16),
                       &g_sp1h[q * 256 + seg * 8]);
        }
        CP_COMMIT();
    }

    // ---- prologue: per-n consts ----
    c0s[tid]  = g_c0 [n * DZ_ + tid];
    gz1s[tid] = g_gz1[n * DZ_ + tid];
    c1s[tid]  = g_c1 [n * DZ_ + tid];
    gk2s[tid] = g_gk2[n * DZ_ + tid];
    if (tid < DY_) {
        gy1s[tid] = g_gy1[n * DY_ + tid];
        yws[tid]  = Y[n * DY_ + tid] - g_w2d[n * DY_ + tid];
    }
    {   // wy0f[z][d] = Wy0[z][d] * gy0[n][d], stride 12 floats
        const int z = tid;
        float4 wa = *(const float4*)&Wy0[z * 8];
        float4 wb = *(const float4*)&Wy0[z * 8 + 4];
        float4 ga = *(const float4*)&g_gy0[n * DY_];
        float4 gb = *(const float4*)&g_gy0[n * DY_ + 4];
        *(float4*)(wy0f + z * 12)     = make_float4(wa.x*ga.x, wa.y*ga.y, wa.z*ga.z, wa.w*ga.w);
        *(float4*)(wy0f + z * 12 + 4) = make_float4(wb.x*gb.x, wb.y*gb.y, wb.z*gb.z, wb.w*gb.w);
    }
    float ur[8];
    {
        float4 u0 = *(const float4*)&U[(m0 + mrow) * 8];
        float4 u1 = *(const float4*)&U[(m0 + mrow) * 8 + 4];
        ur[0]=u0.x; ur[1]=u0.y; ur[2]=u0.z; ur[3]=u0.w;
        ur[4]=u1.x; ur[5]=u1.y; ur[6]=u1.z; ur[7]=u1.w;
    }
    __syncthreads();

    fill_A64(smem + SM_A, 0, wy0f, c0s, gz1s, ur, mrow, s);
    CP_WAIT0();
    __syncthreads();

    float acc[2][8][4];
    #pragma unroll
    for (int i = 0; i < 2; ++i)
        #pragma unroll
        for (int j = 0; j < 8; ++j)
            #pragma unroll
            for (int q = 0; q < 4; ++q) acc[i][j][q] = 0.f;

    // ---- main loop: 4 real 64-z chunks + 1 pseudo k16 chunk ----
    // order per round: cp.async issue -> MMA -> fill next -> wait -> barrier
    #pragma unroll
    for (int c = 0; c < 5; ++c) {
        const int buf = c & 1, nb = buf ^ 1;

        // 1) issue next W cp.async early (rounds 0..2 stage chunks 1..3)
        if (c < 3) {
            const int z0n = (c + 1) * 64;
            const uint32_t Wdst = sb + SM_W + nb * WBUF;
            #pragma unroll
            for (int it = 0; it < 8; ++it) {
                int idx = it * 256 + tid;
                int q = idx >> 3, seg = idx & 7;
                CP_ASYNC16(Wdst + (uint32_t)(q * RS + seg * 16),
                           &g_sp1h[q * 256 + z0n + seg * 8]);
            }
            CP_COMMIT();
        }

        // 2) MMA on current buffer (tensor pipe busy from here)
        {
            const uint32_t aoff = buf * ABUF;
            const uint32_t woff = buf * WBUF;
            const int nks = (c == 4) ? 1 : 4;
            #pragma unroll
            for (int ks = 0; ks < 4; ++ks) {
                if (ks >= nks) break;
                const uint32_t kb = ks * 32;
                uint32_t a0[4], a1[4];
                LDSM_X4(a0[0], a0[1], a0[2], a0[3], a_base[0] + aoff + kb);
                LDSM_X4(a1[0], a1[1], a1[2], a1[3], a_base[1] + aoff + kb);
                #pragma unroll
                for (int jp = 0; jp < 4; ++jp) {
                    uint32_t b[4];
                    LDSM_X4(b[0], b[1], b[2], b[3], b_base[jp] + woff + kb);
                    mma_f16(acc[0][jp * 2],     a0, b[0], b[1]);
                    mma_f16(acc[1][jp * 2],     a1, b[0], b[1]);
                    mma_f16(acc[0][jp * 2 + 1], a0, b[2], b[3]);
                    mma_f16(acc[1][jp * 2 + 1], a1, b[2], b[3]);
                }
            }
        }

        // 3) fill next A chunk (FFMA overlaps tensor drain)
        if (c < 3) {
            fill_A64(smem + SM_A + nb * ABUF, (c + 1) * 64, wy0f, c0s, gz1s, ur, mrow, s);
        } else if (c == 3) {
            // pseudo chunk (k16): A[m][0..7]=U, 8..15=0; W[q][0..7]=Wy1*gy1
            char* Adst = smem + SM_A + nb * ABUF;
            if (s == 0) {
                uint4 av, zv;
                av.x = pack_h2(ur[0], ur[1]); av.y = pack_h2(ur[2], ur[3]);
                av.z = pack_h2(ur[4], ur[5]); av.w = pack_h2(ur[6], ur[7]);
                zv = make_uint4(0, 0, 0, 0);
                *(uint4*)(Adst + mrow * RS)      = av;
                *(uint4*)(Adst + mrow * RS + 16) = zv;
            }
            char* Wdst = smem + SM_W + nb * WBUF;
            const int q = tid;
            float4 w0 = *(const float4*)&Wy1[q * 8];
            float4 w1 = *(const float4*)&Wy1[q * 8 + 4];
            uint4 wv;
            wv.x = pack_h2(w0.x * gy1s[0], w0.y * gy1s[1]);
            wv.y = pack_h2(w0.z * gy1s[2], w0.w * gy1s[3]);
            wv.z = pack_h2(w1.x * gy1s[4], w1.y * gy1s[5]);
            wv.w = pack_h2(w1.z * gy1s[6], w1.w * gy1s[7]);
            *(uint4*)(Wdst + q * RS)      = wv;
            *(uint4*)(Wdst + q * RS + 16) = make_uint4(0, 0, 0, 0);
        }

        // 4) drain cp.async for the chunk staged this round, then barrier
        if (c < 3) CP_WAIT0();
        __syncthreads();
    }

    // ---- epilogue: phi over this CTA's full 256 k ----
    float p[4] = {0.f, 0.f, 0.f, 0.f};
    #pragma unroll
    for (int j = 0; j < 8; ++j) {
        const int q = wq * 64 + j * 8 + 2 * t4;
        const float ca = c1s[q],  cb = c1s[q + 1];
        const float ga = gk2s[q], gb = gk2s[q + 1];
        #pragma unroll
        for (int i = 0; i < 2; ++i) {
            p[i*2+0] = fmaf(fmaxf(acc[i][j][0] + ca, 0.f), ga, p[i*2+0]);
            p[i*2+0] = fmaf(fmaxf(acc[i][j][1] + cb, 0.f), gb, p[i*2+0]);
            p[i*2+1] = fmaf(fmaxf(acc[i][j][2] + ca, 0.f), ga, p[i*2+1]);
            p[i*2+1] = fmaf(fmaxf(acc[i][j][3] + cb, 0.f), gb, p[i*2+1]);
        }
    }
    #pragma unroll
    for (int idx = 0; idx < 4; ++idx) {
        float v = p[idx];
        v += __shfl_xor_sync(0xffffffffu, v, 1);
        v += __shfl_xor_sync(0xffffffffu, v, 2);
        if (t4 == 0) {
            const int i = idx >> 1, h = idx & 1;
            phiB[wq * 64 + wm * 32 + i * 16 + h * 8 + g] = v;
        }
    }
    __syncthreads();
    if (tid < 64) {
        float phi = phiB[tid] + phiB[64 + tid] + phiB[128 + tid] + phiB[192 + tid];
        float4 u0 = *(const float4*)&U[(m0 + tid) * 8];
        float4 u1 = *(const float4*)&U[(m0 + tid) * 8 + 4];
        float sl = -g_c2[n] - phi;
        sl = fmaf(u0.x, yws[0], sl); sl = fmaf(u0.y, yws[1], sl);
        sl = fmaf(u0.z, yws[2], sl); sl = fmaf(u0.w, yws[3], sl);
        sl = fmaf(u1.x, yws[4], sl); sl = fmaf(u1.y, yws[5], sl);
        sl = fmaf(u1.z, yws[6], sl); sl = fmaf(u1.w, yws[7], sl);
        g_slack[n * M_ + m0 + tid] = sl;
    }
}

// ---------------- kernel 3: row-wise stable logsumexp ----------------
__global__ void lse_kernel(float* __restrict__ out) {
    __shared__ float wred[8];
    __shared__ float bmax_s;
    const int n = blockIdx.x, tid = threadIdx.x;
    const int lane = tid & 31, warp = tid >> 5;

    float s[8];
    #pragma unroll
    for (int i = 0; i < 8; i++) s[i] = g_slack[n * M_ + tid + i * 256];

    float mx = s[0];
    #pragma unroll
    for (int i = 1; i < 8; i++) mx = fmaxf(mx, s[i]);
    #pragma unroll
    for (int off = 16; off; off >>= 1)
        mx = fmaxf(mx, __shfl_xor_sync(0xffffffffu, mx, off));
    if (lane == 0) wred[warp] = mx;
    __syncthreads();
    if (tid == 0) {
        float m2 = wred[0];
        #pragma unroll
        for (int w = 1; w < 8; w++) m2 = fmaxf(m2, wred[w]);
        bmax_s = m2;
    }
    __syncthreads();
    const float bmax = bmax_s;

    float sum = 0.f;
    #pragma unroll
    for (int i = 0; i < 8; i++) sum += expf((s[i] - bmax) * 100.f);
    #pragma unroll
    for (int off = 16; off; off >>= 1)
        sum += __shfl_xor_sync(0xffffffffu, sum, off);
    __syncthreads();
    if (lane == 0) wred[warp] = sum;
    __syncthreads();
    if (tid == 0) {
        float tot = 0.f;
        #pragma unroll
        for (int w = 0; w < 8; w++) tot += wred[w];
        out[n] = 0.01f * (logf(tot) - logf(2048.0f)) + bmax;
    }
}

// ---------------- launch ----------------
extern "C" void kernel_launch(void* const* d_in, const int* in_sizes, int n_in,
                              void* d_out, int out_size) {
    const float* X    = (const float*)d_in[0];
    const float* U    = (const float*)d_in[1];
    const float* Y    = (const float*)d_in[2];
    const float* Wt0  = (const float*)d_in[3];
    const float* bt0  = (const float*)d_in[4];
    const float* Wt1  = (const float*)d_in[5];
    const float* bt1  = (const float*)d_in[6];
    const float* Wyu0 = (const float*)d_in[7];
    const float* byu0 = (const float*)d_in[8];
    const float* Wy0  = (const float*)d_in[9];
    const float* Wu0  = (const float*)d_in[10];
    const float* b0   = (const float*)d_in[11];
    const float* Wzu1 = (const float*)d_in[12];
    const float* bzu1 = (const float*)d_in[13];
    const float* Wz1  = (const float*)d_in[14];
    const float* Wyu1 = (const float*)d_in[15];
    const float* byu1 = (const float*)d_in[16];
    const float* Wy1  = (const float*)d_in[17];
    const float* Wu1  = (const float*)d_in[18];
    const float* b1   = (const float*)d_in[19];
    const float* Wzu2 = (const float*)d_in[20];
    const float* bzu2 = (const float*)d_in[21];
    const float* Wz2  = (const float*)d_in[22];
    const float* Wyu2 = (const float*)d_in[23];
    const float* byu2 = (const float*)d_in[24];
    const float* Wy2  = (const float*)d_in[25];
    const float* Wu2  = (const float*)d_in[26];
    const float* b2   = (const float*)d_in[27];

    cudaFuncSetAttribute(main_mma_kernel,
                         cudaFuncAttributeMaxDynamicSharedMemorySize, SMEM_BYTES);

    setup_kernel<<<128, 256>>>(X, Wt0, bt0, Wt1, bt1, Wyu0, byu0, Wu0, b0,
                               Wzu1, bzu1, Wyu1, byu1, Wu1, b1,
                               Wzu2, bzu2, Wz2, Wyu2, byu2, Wy2, Wu2, b2, Wz1);
    dim3 grid(32, 128);
    main_mma_kernel<<<grid, 256, SMEM_BYTES>>>(U, Y, Wy0, Wy1);
    lse_kernel<<<128, 256>>>((float*)d_out);
}

// round 13
// speedup vs baseline: 1.9366x; 1.4806x over previous
#include <cuda_runtime.h>
#include <cuda_fp16.h>
#include <math.h>
#include <stdint.h>

// Problem dims
#define N_  128
#define M_  2048
#define DX_ 64
#define DY_ 8
#define DU_ 256
#define DZ_ 256

// ---------------- device scratch (static, no allocations) ----------------
__device__ __align__(16) __half g_sp1h[DZ_ * DZ_];  // fp16(softplus(Wz1)) [k][z]
__device__ __align__(16) float g_gy0[N_ * DY_];
__device__ __align__(16) float g_c0 [N_ * DZ_];
__device__ __align__(16) float g_gz1[N_ * DZ_];
__device__ __align__(16) float g_gy1[N_ * DY_];
__device__ __align__(16) float g_c1 [N_ * DZ_];
__device__ __align__(16) float g_gk2[N_ * DZ_];     // gz2 * softplus(Wz2)
__device__ __align__(16) float g_w2d[N_ * DY_];     // gy2 * Wy2
__device__ __align__(16) float g_c2 [N_];
__device__ __align__(16) float g_slack[N_ * M_];

__device__ __forceinline__ float softplus_f(float x) {
    return fmaxf(x, 0.f) + log1pf(expf(-fabsf(x)));
}

#define CP_ASYNC16(dst, src) \
    asm volatile("cp.async.cg.shared.global [%0], [%1], 16;" \
        :: "r"((uint32_t)(dst)), "l"(src) : "memory")
#define CP_COMMIT() asm volatile("cp.async.commit_group;" ::: "memory")
#define CP_WAIT0()  asm volatile("cp.async.wait_group 0;" ::: "memory")

__device__ __forceinline__ uint32_t smem_u32(const void* p) {
    uint32_t a;
    asm("{ .reg .u64 t; cvta.to.shared.u64 t, %1; cvt.u32.u64 %0, t; }"
        : "=r"(a) : "l"(p));
    return a;
}

// m16n8k16 fp16 MMA, fp32 accumulate
__device__ __forceinline__ void mma_f16(float* c, const uint32_t* a,
                                        uint32_t b0, uint32_t b1) {
    asm volatile(
        "mma.sync.aligned.m16n8k16.row.col.f32.f16.f16.f32 "
        "{%0,%1,%2,%3}, {%4,%5,%6,%7}, {%8,%9}, {%0,%1,%2,%3};"
        : "+f"(c[0]), "+f"(c[1]), "+f"(c[2]), "+f"(c[3])
        : "r"(a[0]), "r"(a[1]), "r"(a[2]), "r"(a[3]), "r"(b0), "r"(b1));
}

#define LDSM_X4(r0, r1, r2, r3, addr) \
    asm volatile("ldmatrix.sync.aligned.m8n8.x4.shared.b16 {%0,%1,%2,%3}, [%4];" \
        : "=r"(r0), "=r"(r1), "=r"(r2), "=r"(r3) : "r"(addr))

__device__ __forceinline__ uint32_t pack_h2(float lo, float hi) {
    __half2 h = __floats2half2_rn(lo, hi);
    return *(uint32_t*)&h;
}

// ---- vectorized dot helpers: float4 weight loads, 4 accumulator chains ----
__device__ __forceinline__ float dot64v(const float* __restrict__ W,
                                        const float4* vs) {
    const float4* w4 = (const float4*)W;
    float s0 = 0.f, s1 = 0.f, s2 = 0.f, s3 = 0.f;
    #pragma unroll
    for (int i = 0; i < 16; i += 4) {
        float4 w0 = w4[i],     x0 = vs[i];
        float4 w1 = w4[i + 1], x1 = vs[i + 1];
        float4 w2 = w4[i + 2], x2 = vs[i + 2];
        float4 w3 = w4[i + 3], x3 = vs[i + 3];
        s0 = fmaf(w0.x, x0.x, s0); s0 = fmaf(w0.y, x0.y, s0);
        s0 = fmaf(w0.z, x0.z, s0); s0 = fmaf(w0.w, x0.w, s0);
        s1 = fmaf(w1.x, x1.x, s1); s1 = fmaf(w1.y, x1.y, s1);
        s1 = fmaf(w1.z, x1.z, s1); s1 = fmaf(w1.w, x1.w, s1);
        s2 = fmaf(w2.x, x2.x, s2); s2 = fmaf(w2.y, x2.y, s2);
        s2 = fmaf(w2.z, x2.z, s2); s2 = fmaf(w2.w, x2.w, s2);
        s3 = fmaf(w3.x, x3.x, s3); s3 = fmaf(w3.y, x3.y, s3);
        s3 = fmaf(w3.z, x3.z, s3); s3 = fmaf(w3.w, x3.w, s3);
    }
    return (s0 + s1) + (s2 + s3);
}

__device__ __forceinline__ float dot256v(const float* __restrict__ W,
                                         const float4* vs) {
    const float4* w4 = (const float4*)W;
    float s0 = 0.f, s1 = 0.f, s2 = 0.f, s3 = 0.f;
    #pragma unroll
    for (int i = 0; i < 64; i += 4) {
        float4 w0 = w4[i],     x0 = vs[i];
        float4 w1 = w4[i + 1], x1 = vs[i + 1];
        float4 w2 = w4[i + 2], x2 = vs[i + 2];
        float4 w3 = w4[i + 3], x3 = vs[i + 3];
        s0 = fmaf(w0.x, x0.x, s0); s0 = fmaf(w0.y, x0.y, s0);
        s0 = fmaf(w0.z, x0.z, s0); s0 = fmaf(w0.w, x0.w, s0);
        s1 = fmaf(w1.x, x1.x, s1); s1 = fmaf(w1.y, x1.y, s1);
        s1 = fmaf(w1.z, x1.z, s1); s1 = fmaf(w1.w, x1.w, s1);
        s2 = fmaf(w2.x, x2.x, s2); s2 = fmaf(w2.y, x2.y, s2);
        s2 = fmaf(w2.z, x2.z, s2); s2 = fmaf(w2.w, x2.w, s2);
        s3 = fmaf(w3.x, x3.x, s3); s3 = fmaf(w3.y, x3.y, s3);
        s3 = fmaf(w3.z, x3.z, s3); s3 = fmaf(w3.w, x3.w, s3);
    }
    return (s0 + s1) + (s2 + s3);
}

// ---------------- kernel 0: fp16(softplus(Wz1)) ----------------
__global__ void sp1_kernel(const float* __restrict__ Wz1) {
    int i = blockIdx.x * 256 + threadIdx.x;
    g_sp1h[i] = __float2half_rn(softplus_f(Wz1[i]));
}

// ---------------- kernel 1: per-n setup (vectorized) ----------------
__global__ void setup_kernel(
    const float* __restrict__ X,
    const float* __restrict__ Wt0,  const float* __restrict__ bt0,
    const float* __restrict__ Wt1,  const float* __restrict__ bt1,
    const float* __restrict__ Wyu0, const float* __restrict__ byu0,
    const float* __restrict__ Wu0,  const float* __restrict__ b0,
    const float* __restrict__ Wzu1, const float* __restrict__ bzu1,
    const float* __restrict__ Wyu1, const float* __restrict__ byu1,
    const float* __restrict__ Wu1,  const float* __restrict__ b1,
    const float* __restrict__ Wzu2, const float* __restrict__ bzu2,
    const float* __restrict__ Wz2,
    const float* __restrict__ Wyu2, const float* __restrict__ byu2,
    const float* __restrict__ Wy2,
    const float* __restrict__ Wu2,  const float* __restrict__ b2)
{
    __shared__ __align__(16) float xs[DX_];
    __shared__ __align__(16) float u1s[DU_];
    __shared__ __align__(16) float u2s[DU_];
    __shared__ float red[256];
    const int n = blockIdx.x;
    const int k = threadIdx.x;

    if (k < 16) ((float4*)xs)[k] = ((const float4*)(X + n * DX_))[k];
    __syncthreads();
    const float4* xs4 = (const float4*)xs;

    // u1 = relu(X @ Wt0^T + bt0)
    u1s[k] = fmaxf(dot64v(&Wt0[k * DX_], xs4) + bt0[k], 0.f);
    // c0 = X @ Wu0^T + b0
    g_c0[n * DZ_ + k] = dot64v(&Wu0[k * DX_], xs4) + b0[k];
    if (k < DY_)
        g_gy0[n * DY_ + k] = dot64v(&Wyu0[k * DX_], xs4) + byu0[k];
    __syncthreads();
    const float4* u14 = (const float4*)u1s;

    // u2 = relu(u1 @ Wt1^T + bt1)
    float u2v = fmaxf(dot256v(&Wt1[k * DU_], u14) + bt1[k], 0.f);
    u2s[k] = u2v;
    // gz1 = relu(u1 @ Wzu1^T + bzu1)
    g_gz1[n * DZ_ + k] = fmaxf(dot256v(&Wzu1[k * DU_], u14) + bzu1[k], 0.f);
    // c1 = u1 @ Wu1^T + b1
    g_c1[n * DZ_ + k] = dot256v(&Wu1[k * DU_], u14) + b1[k];
    if (k < DY_)
        g_gy1[n * DY_ + k] = dot256v(&Wyu1[k * DU_], u14) + byu1[k];
    __syncthreads();
    const float4* u24 = (const float4*)u2s;

    // gk2 = relu(u2 @ Wzu2^T + bzu2) * softplus(Wz2)
    g_gk2[n * DZ_ + k] =
        fmaxf(dot256v(&Wzu2[k * DU_], u24) + bzu2[k], 0.f) * softplus_f(Wz2[k]);
    if (k < DY_)
        g_w2d[n * DY_ + k] = (dot256v(&Wyu2[k * DU_], u24) + byu2[k]) * Wy2[k];

    // c2 = u2 @ Wu2 + b2  (block reduce)
    red[k] = u2v * Wu2[k];
    __syncthreads();
    for (int st = 128; st > 0; st >>= 1) {
        if (k < st) red[k] += red[k + st];
        __syncthreads();
    }
    if (k == 0) g_c2[n] = red[0] + b2[0];
}

// ---------------- kernel 2: fp16 HMMA GEMM + full phi + slack ----------------
// grid = (32, 128): x -> 64-row m-tile, y -> n.  CTA: 64m x 256k_out.
// 8 warps: wm = wid&1 (32 m rows), wq = wid>>1 (64 k cols).
// K loop: 4 chunks of 64 z + 1 k16 pseudo chunk; double buffered, ldmatrix frags.
// Row stride 144 B (9 x 16B) -> conflict-free ldmatrix.  (R8 structure.)

#define RS    144                   // row stride bytes
#define SM_W     0                  // 2 x 256*144 = 73728
#define SM_A     73728              // 2 x 64*144  = 18432
#define SM_WY0F  92160              // 256 x 12 floats = 12288
#define SM_C0    104448             // 256 floats
#define SM_GZ1   105472
#define SM_C1    106496
#define SM_GK2   107520
#define SM_GY1   108544             // 8 floats (pad 64B)
#define SM_YW    108608
#define SM_PHI   108672             // 256 floats
#define SMEM_BYTES 109696
#define WBUF  36864                 // 256*144
#define ABUF  9216                  // 64*144

extern __shared__ __align__(16) char smem[];

// fill one 64-z A chunk: thread owns row mrow, z quarter s (16 z)
__device__ __forceinline__ void fill_A64(char* Adst, int z0,
                                         const float* wy0f, const float* c0s,
                                         const float* gz1s, const float* ur,
                                         int mrow, int s)
{
    float o[16];
    #pragma unroll
    for (int jj = 0; jj < 16; ++jj) {
        const int j = (jj + s) & 15;           // bank-rotation schedule
        const int z = z0 + s * 16 + j;
        const float4 w0 = *(const float4*)(wy0f + z * 12);
        const float4 w1 = *(const float4*)(wy0f + z * 12 + 4);
        float v = c0s[z];
        v = fmaf(ur[0], w0.x, v); v = fmaf(ur[1], w0.y, v);
        v = fmaf(ur[2], w0.z, v); v = fmaf(ur[3], w0.w, v);
        v = fmaf(ur[4], w1.x, v); v = fmaf(ur[5], w1.y, v);
        v = fmaf(ur[6], w1.z, v); v = fmaf(ur[7], w1.w, v);
        o[j] = fmaxf(v, 0.f) * gz1s[z];
    }
    uint4 p0, p1;
    p0.x = pack_h2(o[0],  o[1]);  p0.y = pack_h2(o[2],  o[3]);
    p0.z = pack_h2(o[4],  o[5]);  p0.w = pack_h2(o[6],  o[7]);
    p1.x = pack_h2(o[8],  o[9]);  p1.y = pack_h2(o[10], o[11]);
    p1.z = pack_h2(o[12], o[13]); p1.w = pack_h2(o[14], o[15]);
    char* dst = Adst + mrow * RS + s * 32;
    *(uint4*)(dst)      = p0;
    *(uint4*)(dst + 16) = p1;
}

__global__ __launch_bounds__(256, 2) void main_mma_kernel(
    const float* __restrict__ U,
    const float* __restrict__ Y,
    const float* __restrict__ Wy0,
    const float* __restrict__ Wy1)
{
    const int tid  = threadIdx.x;
    const int lane = tid & 31;
    const int wid  = tid >> 5;
    const int g    = lane >> 2;     // groupID
    const int t4   = lane & 3;      // thread-in-group
    const int wm   = wid & 1;       // warp m-group (32 rows)
    const int wq   = wid >> 1;      // warp k-col group (64 cols)
    const int n    = blockIdx.y;
    const int m0   = blockIdx.x * 64;

    float* wy0f = (float*)(smem + SM_WY0F);
    float* c0s  = (float*)(smem + SM_C0);
    float* gz1s = (float*)(smem + SM_GZ1);
    float* c1s  = (float*)(smem + SM_C1);
    float* gk2s = (float*)(smem + SM_GK2);
    float* gy1s = (float*)(smem + SM_GY1);
    float* yws  = (float*)(smem + SM_YW);
    float* phiB = (float*)(smem + SM_PHI);
    const uint32_t sb = smem_u32(smem);

    // A-fill assignment
    const int mrow = tid >> 2;      // 0..63
    const int s    = tid & 3;       // z quarter

    // ldmatrix per-lane base addresses (buf 0)
    const int mi = lane >> 3, r = lane & 7;
    uint32_t a_base[2], b_base[4];
    #pragma unroll
    for (int i = 0; i < 2; ++i)
        a_base[i] = sb + SM_A + (uint32_t)((wm * 32 + i * 16 + (mi & 1) * 8 + r) * RS
                                           + (mi >> 1) * 16);
    #pragma unroll
    for (int jp = 0; jp < 4; ++jp)
        b_base[jp] = sb + SM_W + (uint32_t)((wq * 64 + jp * 16 + (mi >> 1) * 8 + r) * RS
                                            + (mi & 1) * 16);

    // ---- kick off W chunk 0 cp.async ----
    {
        const uint32_t Wdst = sb + SM_W;
        #pragma unroll
        for (int it = 0; it < 8; ++it) {
            int idx = it * 256 + tid;
            int q = idx >> 3, seg = idx & 7;
            CP_ASYNC16(Wdst + (uint32_t)(q * RS + seg * 16),
                       &g_sp1h[q * 256 + seg * 8]);
        }
        CP_COMMIT();
    }

    // ---- prologue: per-n consts ----
    c0s[tid]  = g_c0 [n * DZ_ + tid];
    gz1s[tid] = g_gz1[n * DZ_ + tid];
    c1s[tid]  = g_c1 [n * DZ_ + tid];
    gk2s[tid] = g_gk2[n * DZ_ + tid];
    if (tid < DY_) {
        gy1s[tid] = g_gy1[n * DY_ + tid];
        yws[tid]  = Y[n * DY_ + tid] - g_w2d[n * DY_ + tid];
    }
    {   // wy0f[z][d] = Wy0[z][d] * gy0[n][d], stride 12 floats
        const int z = tid;
        float4 wa = *(const float4*)&Wy0[z * 8];
        float4 wb = *(const float4*)&Wy0[z * 8 + 4];
        float4 ga = *(const float4*)&g_gy0[n * DY_];
        float4 gb = *(const float4*)&g_gy0[n * DY_ + 4];
        *(float4*)(wy0f + z * 12)     = make_float4(wa.x*ga.x, wa.y*ga.y, wa.z*ga.z, wa.w*ga.w);
        *(float4*)(wy0f + z * 12 + 4) = make_float4(wb.x*gb.x, wb.y*gb.y, wb.z*gb.z, wb.w*gb.w);
    }
    float ur[8];
    {
        float4 u0 = *(const float4*)&U[(m0 + mrow) * 8];
        float4 u1 = *(const float4*)&U[(m0 + mrow) * 8 + 4];
        ur[0]=u0.x; ur[1]=u0.y; ur[2]=u0.z; ur[3]=u0.w;
        ur[4]=u1.x; ur[5]=u1.y; ur[6]=u1.z; ur[7]=u1.w;
    }
    __syncthreads();

    fill_A64(smem + SM_A, 0, wy0f, c0s, gz1s, ur, mrow, s);
    CP_WAIT0();
    __syncthreads();

    float acc[2][8][4];
    #pragma unroll
    for (int i = 0; i < 2; ++i)
        #pragma unroll
        for (int j = 0; j < 8; ++j)
            #pragma unroll
            for (int q = 0; q < 4; ++q) acc[i][j][q] = 0.f;

    // ---- main loop: 4 real 64-z chunks + 1 pseudo k16 chunk ----
    #pragma unroll
    for (int c = 0; c < 5; ++c) {
        const int buf = c & 1, nb = buf ^ 1;

        if (c < 4) {
            if (c + 1 < 4) {
                const int z0n = (c + 1) * 64;
                const uint32_t Wdst = sb + SM_W + nb * WBUF;
                #pragma unroll
                for (int it = 0; it < 8; ++it) {
                    int idx = it * 256 + tid;
                    int q = idx >> 3, seg = idx & 7;
                    CP_ASYNC16(Wdst + (uint32_t)(q * RS + seg * 16),
                               &g_sp1h[q * 256 + z0n + seg * 8]);
                }
                CP_COMMIT();
                fill_A64(smem + SM_A + nb * ABUF, z0n, wy0f, c0s, gz1s, ur, mrow, s);
            } else {
                // pseudo chunk (k16): A[m][0..7]=U, 8..15=0; W[q][0..7]=Wy1*gy1
                char* Adst = smem + SM_A + nb * ABUF;
                if (s == 0) {
                    uint4 av, zv;
                    av.x = pack_h2(ur[0], ur[1]); av.y = pack_h2(ur[2], ur[3]);
                    av.z = pack_h2(ur[4], ur[5]); av.w = pack_h2(ur[6], ur[7]);
                    zv = make_uint4(0, 0, 0, 0);
                    *(uint4*)(Adst + mrow * RS)      = av;
                    *(uint4*)(Adst + mrow * RS + 16) = zv;
                }
                char* Wdst = smem + SM_W + nb * WBUF;
                const int q = tid;
                float4 w0 = *(const float4*)&Wy1[q * 8];
                float4 w1 = *(const float4*)&Wy1[q * 8 + 4];
                uint4 wv;
                wv.x = pack_h2(w0.x * gy1s[0], w0.y * gy1s[1]);
                wv.y = pack_h2(w0.z * gy1s[2], w0.w * gy1s[3]);
                wv.z = pack_h2(w1.x * gy1s[4], w1.y * gy1s[5]);
                wv.w = pack_h2(w1.z * gy1s[6], w1.w * gy1s[7]);
                *(uint4*)(Wdst + q * RS)      = wv;
                *(uint4*)(Wdst + q * RS + 16) = make_uint4(0, 0, 0, 0);
            }
        }

        // MMA on current buffer
        {
            const uint32_t aoff = buf * ABUF;
            const uint32_t woff = buf * WBUF;
            const int nks = (c == 4) ? 1 : 4;
            #pragma unroll
            for (int ks = 0; ks < 4; ++ks) {
                if (ks >= nks) break;
                const uint32_t kb = ks * 32;
                uint32_t a0[4], a1[4];
                LDSM_X4(a0[0], a0[1], a0[2], a0[3], a_base[0] + aoff + kb);
                LDSM_X4(a1[0], a1[1], a1[2], a1[3], a_base[1] + aoff + kb);
                #pragma unroll
                for (int jp = 0; jp < 4; ++jp) {
                    uint32_t b[4];
                    LDSM_X4(b[0], b[1], b[2], b[3], b_base[jp] + woff + kb);
                    mma_f16(acc[0][jp * 2],     a0, b[0], b[1]);
                    mma_f16(acc[1][jp * 2],     a1, b[0], b[1]);
                    mma_f16(acc[0][jp * 2 + 1], a0, b[2], b[3]);
                    mma_f16(acc[1][jp * 2 + 1], a1, b[2], b[3]);
                }
            }
        }
        if (c < 3) CP_WAIT0();
        __syncthreads();
    }

    // ---- epilogue: phi over this CTA's full 256 k ----
    float p[4] = {0.f, 0.f, 0.f, 0.f};
    #pragma unroll
    for (int j = 0; j < 8; ++j) {
        const int q = wq * 64 + j * 8 + 2 * t4;
        const float ca = c1s[q],  cb = c1s[q + 1];
        const float ga = gk2s[q], gb = gk2s[q + 1];
        #pragma unroll
        for (int i = 0; i < 2; ++i) {
            p[i*2+0] = fmaf(fmaxf(acc[i][j][0] + ca, 0.f), ga, p[i*2+0]);
            p[i*2+0] = fmaf(fmaxf(acc[i][j][1] + cb, 0.f), gb, p[i*2+0]);
            p[i*2+1] = fmaf(fmaxf(acc[i][j][2] + ca, 0.f), ga, p[i*2+1]);
            p[i*2+1] = fmaf(fmaxf(acc[i][j][3] + cb, 0.f), gb, p[i*2+1]);
        }
    }
    #pragma unroll
    for (int idx = 0; idx < 4; ++idx) {
        float v = p[idx];
        v += __shfl_xor_sync(0xffffffffu, v, 1);
        v += __shfl_xor_sync(0xffffffffu, v, 2);
        if (t4 == 0) {
            const int i = idx >> 1, h = idx & 1;
            phiB[wq * 64 + wm * 32 + i * 16 + h * 8 + g] = v;
        }
    }
    __syncthreads();
    if (tid < 64) {
        float phi = phiB[tid] + phiB[64 + tid] + phiB[128 + tid] + phiB[192 + tid];
        float4 u0 = *(const float4*)&U[(m0 + tid) * 8];
        float4 u1 = *(const float4*)&U[(m0 + tid) * 8 + 4];
        float sl = -g_c2[n] - phi;
        sl = fmaf(u0.x, yws[0], sl); sl = fmaf(u0.y, yws[1], sl);
        sl = fmaf(u0.z, yws[2], sl); sl = fmaf(u0.w, yws[3], sl);
        sl = fmaf(u1.x, yws[4], sl); sl = fmaf(u1.y, yws[5], sl);
        sl = fmaf(u1.z, yws[6], sl); sl = fmaf(u1.w, yws[7], sl);
        g_slack[n * M_ + m0 + tid] = sl;
    }
}

// ---------------- kernel 3: row-wise stable logsumexp ----------------
__global__ void lse_kernel(float* __restrict__ out) {
    __shared__ float wred[8];
    __shared__ float bmax_s;
    const int n = blockIdx.x, tid = threadIdx.x;
    const int lane = tid & 31, warp = tid >> 5;

    float s[8];
    #pragma unroll
    for (int i = 0; i < 8; i++) s[i] = g_slack[n * M_ + tid + i * 256];

    float mx = s[0];
    #pragma unroll
    for (int i = 1; i < 8; i++) mx = fmaxf(mx, s[i]);
    #pragma unroll
    for (int off = 16; off; off >>= 1)
        mx = fmaxf(mx, __shfl_xor_sync(0xffffffffu, mx, off));
    if (lane == 0) wred[warp] = mx;
    __syncthreads();
    if (tid == 0) {
        float m2 = wred[0];
        #pragma unroll
        for (int w = 1; w < 8; w++) m2 = fmaxf(m2, wred[w]);
        bmax_s = m2;
    }
    __syncthreads();
    const float bmax = bmax_s;

    float sum = 0.f;
    #pragma unroll
    for (int i = 0; i < 8; i++) sum += expf((s[i] - bmax) * 100.f);
    #pragma unroll
    for (int off = 16; off; off >>= 1)
        sum += __shfl_xor_sync(0xffffffffu, sum, off);
    __syncthreads();
    if (lane == 0) wred[warp] = sum;
    __syncthreads();
    if (tid == 0) {
        float tot = 0.f;
        #pragma unroll
        for (int w = 0; w < 8; w++) tot += wred[w];
        out[n] = 0.01f * (logf(tot) - logf(2048.0f)) + bmax;
    }
}

// ---------------- launch ----------------
extern "C" void kernel_launch(void* const* d_in, const int* in_sizes, int n_in,
                              void* d_out, int out_size) {
    const float* X    = (const float*)d_in[0];
    const float* U    = (const float*)d_in[1];
    const float* Y    = (const float*)d_in[2];
    const float* Wt0  = (const float*)d_in[3];
    const float* bt0  = (const float*)d_in[4];
    const float* Wt1  = (const float*)d_in[5];
    const float* bt1  = (const float*)d_in[6];
    const float* Wyu0 = (const float*)d_in[7];
    const float* byu0 = (const float*)d_in[8];
    const float* Wy0  = (const float*)d_in[9];
    const float* Wu0  = (const float*)d_in[10];
    const float* b0   = (const float*)d_in[11];
    const float* Wzu1 = (const float*)d_in[12];
    const float* bzu1 = (const float*)d_in[13];
    const float* Wz1  = (const float*)d_in[14];
    const float* Wyu1 = (const float*)d_in[15];
    const float* byu1 = (const float*)d_in[16];
    const float* Wy1  = (const float*)d_in[17];
    const float* Wu1  = (const float*)d_in[18];
    const float* b1   = (const float*)d_in[19];
    const float* Wzu2 = (const float*)d_in[20];
    const float* bzu2 = (const float*)d_in[21];
    const float* Wz2  = (const float*)d_in[22];
    const float* Wyu2 = (const float*)d_in[23];
    const float* byu2 = (const float*)d_in[24];
    const float* Wy2  = (const float*)d_in[25];
    const float* Wu2  = (const float*)d_in[26];
    const float* b2   = (const float*)d_in[27];

    cudaFuncSetAttribute(main_mma_kernel,
                         cudaFuncAttributeMaxDynamicSharedMemorySize, SMEM_BYTES);

    sp1_kernel<<<256, 256>>>(Wz1);
    setup_kernel<<<128, 256>>>(X, Wt0, bt0, Wt1, bt1, Wyu0, byu0, Wu0, b0,
                               Wzu1, bzu1, Wyu1, byu1, Wu1, b1,
                               Wzu2, bzu2, Wz2, Wyu2, byu2, Wy2, Wu2, b2);
    dim3 grid(32, 128);
    main_mma_kernel<<<grid, 256, SMEM_BYTES>>>(U, Y, Wy0, Wy1);
    lse_kernel<<<128, 256>>>((float*)d_out);
}